// round 8
// baseline (speedup 1.0000x reference)
#include <cuda_runtime.h>
#include <cuda_bf16.h>
#include <cstdint>

#define BB   8
#define SRC  512
#define TGT  128
#define ED   512
#define DD   512
#define TT   4

// Scratch (device globals: allocation-free per harness rules)
// NOTE: g_mp/g_dp now hold Eb = exp(2*mp), Ea = exp(2*dp) (written by gemm_tc).
__device__ float g_mp[BB * SRC * DD];          // 8 MB
__device__ float g_dp[BB * TGT * DD];          // 2 MB
__device__ float g_a [BB * TGT * SRC];         // 2 MB: softmax probabilities
__device__ __nv_bfloat16 g_Ah[5120 * 512];     // A hi (memory rows 0..4095, dec 4096..5119)
__device__ __nv_bfloat16 g_Al[5120 * 512];     // A lo
__device__ __nv_bfloat16 g_Wth[2 * 512 * 512]; // W^T hi: sel 0 = Wa_d, 1 = Wa_m; [n][k]
__device__ __nv_bfloat16 g_Wtl[2 * 512 * 512]; // W^T lo

__device__ __forceinline__ float fast_rcp(float x) {
    float y;
    asm("rcp.approx.f32 %0, %1;" : "=f"(y) : "f"(x));
    return y;
}

__device__ __forceinline__ void cp_async16(void* smem_dst, const void* gmem_src) {
    uint32_t d = (uint32_t)__cvta_generic_to_shared(smem_dst);
    asm volatile("cp.async.ca.shared.global [%0], [%1], 16;\n" :: "r"(d), "l"(gmem_src));
}
#define CP_COMMIT() asm volatile("cp.async.commit_group;\n")
#define CP_WAIT1()  asm volatile("cp.async.wait_group 1;\n")
#define CP_WAIT0()  asm volatile("cp.async.wait_group 0;\n")

__device__ __forceinline__ void ldm_x4(uint32_t* r, uint32_t addr) {
    asm volatile("ldmatrix.sync.aligned.m8n8.x4.shared.b16 {%0,%1,%2,%3}, [%4];"
                 : "=r"(r[0]), "=r"(r[1]), "=r"(r[2]), "=r"(r[3]) : "r"(addr));
}
__device__ __forceinline__ void mma16816(float* c, const uint32_t* a, const uint32_t* b) {
    asm volatile("mma.sync.aligned.m16n8k16.row.col.f32.bf16.bf16.f32 "
                 "{%0,%1,%2,%3}, {%4,%5,%6,%7}, {%8,%9}, {%0,%1,%2,%3};"
                 : "+f"(c[0]), "+f"(c[1]), "+f"(c[2]), "+f"(c[3])
                 : "r"(a[0]), "r"(a[1]), "r"(a[2]), "r"(a[3]), "r"(b[0]), "r"(b[1]));
}

// ---------------------------------------------------------------------------
// Conversion: fp32 -> bf16 (hi, lo) for A = [memory ; dec]  (5120 x 512)
// ---------------------------------------------------------------------------
__global__ void __launch_bounds__(256) conv_a(
    const float* __restrict__ memory, const float* __restrict__ dec)
{
    const int idx = blockIdx.x * 256 + threadIdx.x;          // float4 index
    const float4 v = (idx < 524288) ? ((const float4*)memory)[idx]
                                    : ((const float4*)dec)[idx - 524288];
    float xs[4] = {v.x, v.y, v.z, v.w};
    __nv_bfloat16 h[4], l[4];
    #pragma unroll
    for (int i = 0; i < 4; i++) {
        h[i] = __float2bfloat16(xs[i]);
        l[i] = __float2bfloat16(xs[i] - __bfloat162float(h[i]));
    }
    ((__nv_bfloat162*)g_Ah)[idx * 2]     = __halves2bfloat162(h[0], h[1]);
    ((__nv_bfloat162*)g_Ah)[idx * 2 + 1] = __halves2bfloat162(h[2], h[3]);
    ((__nv_bfloat162*)g_Al)[idx * 2]     = __halves2bfloat162(l[0], l[1]);
    ((__nv_bfloat162*)g_Al)[idx * 2 + 1] = __halves2bfloat162(l[2], l[3]);
}

// ---------------------------------------------------------------------------
// Conversion: W^T hi/lo.  Wt[sel][n][k] = Wa[sel*512 + k][n];  sel 0=Wa_d, 1=Wa_m
// ---------------------------------------------------------------------------
__global__ void __launch_bounds__(256) conv_w(const float* __restrict__ Wa)
{
    __shared__ float s[32][33];
    const int tx = threadIdx.x, ty = threadIdx.y;            // 32 x 8
    const int bx = blockIdx.x, by = blockIdx.y, sel = blockIdx.z;

    #pragma unroll
    for (int j = 0; j < 32; j += 8)
        s[ty + j][tx] = Wa[(size_t)(sel * 512 + by * 32 + ty + j) * 512 + bx * 32 + tx];
    __syncthreads();

    #pragma unroll
    for (int j = 0; j < 32; j += 8) {
        const int n = bx * 32 + ty + j;
        const int k = by * 32 + tx;
        float x = s[tx][ty + j];
        __nv_bfloat16 h = __float2bfloat16(x);
        __nv_bfloat16 l = __float2bfloat16(x - __bfloat162float(h));
        const size_t o = (size_t)(sel * 512 + n) * 512 + k;
        g_Wth[o] = h;
        g_Wtl[o] = l;
    }
}

// ---------------------------------------------------------------------------
// Tensor-core projection GEMM via mma.sync (bf16 3-way split, fp32 accum).
// EPILOGUE: store exp(2*proj) so the score kernel can use
// tanh(a+b) = 1 - 2/(1 + e^{2a} e^{2b})  (rcp rt=8 vs tanh rt=16 on MUFU).
// ---------------------------------------------------------------------------
#define PITCH 48
#define OA_H  0
#define OA_L  6144
#define OW_H  12288
#define OW_L  15360
#define BUFSZ 18432

__global__ void __launch_bounds__(256, 2) gemm_tc()
{
    __shared__ char sm[2 * BUFSZ];                // 36 KB
    const uint32_t sb = (uint32_t)__cvta_generic_to_shared(sm);

    const int tid  = threadIdx.x;
    const int lane = tid & 31;
    const int w    = tid >> 5;
    const int wm   = w >> 1;                      // 0..3 (m)
    const int wn   = w & 1;                       // 0..1 (n)
    const int bn   = blockIdx.x;                  // 0..7
    const int by   = blockIdx.y;                  // 0..39

    const int m_base = by * 128;
    const int sel    = (by < 32) ? 1 : 0;
    float* C = (by < 32) ? (g_mp + (size_t)by * 128 * 512)
                         : (g_dp + (size_t)(by - 32) * 128 * 512);
    const __nv_bfloat16* Wh = g_Wth + (size_t)sel * 512 * 512 + (size_t)bn * 64 * 512;
    const __nv_bfloat16* Wl = g_Wtl + (size_t)sel * 512 * 512 + (size_t)bn * 64 * 512;

    const int ar = tid >> 1, ac = tid & 1;
    const int wr = (tid & 127) >> 1, wc = tid & 1;
    const bool do_w = (tid < 128);

    auto issue = [&](int kc, int buf) {
        char* B = sm + buf * BUFSZ;
        const size_t asrc = (size_t)(m_base + ar) * 512 + kc * 16 + ac * 8;
        cp_async16(B + OA_H + ar * PITCH + ac * 16, g_Ah + asrc);
        cp_async16(B + OA_L + ar * PITCH + ac * 16, g_Al + asrc);
        if (do_w) {
            const size_t wsrc = (size_t)wr * 512 + kc * 16 + wc * 8;
            cp_async16(B + OW_H + wr * PITCH + wc * 16, Wh + wsrc);
            cp_async16(B + OW_L + wr * PITCH + wc * 16, Wl + wsrc);
        }
        CP_COMMIT();
    };

    const uint32_t a_off = (uint32_t)((wm * 32 + (lane & 15)) * PITCH + (lane >> 4) * 16);
    const uint32_t b_off = (uint32_t)((wn * 32 + (lane & 7) + ((lane >> 4) * 8)) * PITCH
                                      + (((lane >> 3) & 1) * 16));

    float acc[2][4][4];
    #pragma unroll
    for (int i = 0; i < 2; i++)
        #pragma unroll
        for (int j = 0; j < 4; j++)
            #pragma unroll
            for (int e = 0; e < 4; e++) acc[i][j][e] = 0.f;

    issue(0, 0);

    for (int kc = 0; kc < 32; kc++) {
        if (kc < 31) { issue(kc + 1, (kc + 1) & 1); CP_WAIT1(); }
        else         { CP_WAIT0(); }
        __syncthreads();

        const uint32_t base = sb + (kc & 1) * BUFSZ;
        uint32_t ah[2][4], al[2][4], bh[2][4], bl[2][4];
        #pragma unroll
        for (int i = 0; i < 2; i++) {
            ldm_x4(ah[i], base + OA_H + a_off + i * 16 * PITCH);
            ldm_x4(al[i], base + OA_L + a_off + i * 16 * PITCH);
        }
        #pragma unroll
        for (int j = 0; j < 2; j++) {
            ldm_x4(bh[j], base + OW_H + b_off + j * 16 * PITCH);
            ldm_x4(bl[j], base + OW_L + b_off + j * 16 * PITCH);
        }

        #pragma unroll
        for (int i = 0; i < 2; i++)
            #pragma unroll
            for (int j = 0; j < 4; j++) {
                const uint32_t* ph = &bh[j >> 1][2 * (j & 1)];
                const uint32_t* pl = &bl[j >> 1][2 * (j & 1)];
                mma16816(acc[i][j], ah[i], ph);
                mma16816(acc[i][j], ah[i], pl);
                mma16816(acc[i][j], al[i], ph);
            }
        __syncthreads();
    }

    // epilogue: store E = exp(2 * proj)
    #pragma unroll
    for (int i = 0; i < 2; i++) {
        const int r0 = wm * 32 + i * 16 + (lane >> 2);
        #pragma unroll
        for (int j = 0; j < 4; j++) {
            const int c0 = bn * 64 + wn * 32 + j * 8 + (lane & 3) * 2;
            *(float2*)(C + (size_t)r0 * 512 + c0) =
                make_float2(__expf(2.f * acc[i][j][0]), __expf(2.f * acc[i][j][1]));
            *(float2*)(C + (size_t)(r0 + 8) * 512 + c0) =
                make_float2(__expf(2.f * acc[i][j][2]), __expf(2.f * acc[i][j][3]));
        }
    }
}

// ---------------------------------------------------------------------------
// Score + masked softmax -> g_a.
// e[t,s] = const - 2 * sum_k Va_k / (1 + Ea[t,k]*Eb[s,k]); const cancels in
// softmax. Inner element: 1 FMA (den) + 1 rcp.approx (MUFU rt=8) + 1 FMA (acc)
// -> 16 elem/cyc/SM ceiling (2x the tanh version).
// Layout identical to measured-best R4: 8 warps, TT=4 t/block, 256-row tile.
// ---------------------------------------------------------------------------
__global__ void __launch_bounds__(256, 4) score_kernel(
    const float* __restrict__ Va,
    const int* __restrict__ mask)
{
    __shared__ float s_mp[256 * 36];
    __shared__ float s_dp[TT * 512];
    __shared__ float s_va[512];
    __shared__ float s_red[TT * 8];

    const int b    = blockIdx.y;
    const int t0   = blockIdx.x * TT;
    const int tid  = threadIdx.x;
    const int lane = tid & 31;
    const int w    = tid >> 5;

    {
        const float4* dpg = (const float4*)(g_dp + (size_t)(b * TGT + t0) * 512);
        ((float4*)s_dp)[tid]       = dpg[tid];
        ((float4*)s_dp)[tid + 256] = dpg[tid + 256];
        if (tid < 128) ((float4*)s_va)[tid] = ((const float4*)Va)[tid];
    }

    float acc[2 * TT];
    #pragma unroll
    for (int i = 0; i < 2 * TT; i++) acc[i] = 0.f;

    const int r0    = tid >> 3;
    const int c4    = (tid & 7) << 2;
    const int myrow = w * 32 + lane;

    #pragma unroll
    for (int stage = 0; stage < 2; stage++) {
        const float* mpg = g_mp + (size_t)(b * SRC + stage * 256) * 512;
        float* ep = acc + stage * TT;
        for (int kc = 0; kc < 512; kc += 32) {
            __syncthreads();
            #pragma unroll
            for (int rr = 0; rr < 256; rr += 32) {
                float4 v = *(const float4*)(mpg + (size_t)(r0 + rr) * 512 + kc + c4);
                *(float4*)(s_mp + (r0 + rr) * 36 + c4) = v;
            }
            __syncthreads();

            const float* mrow_s = s_mp + myrow * 36;
            #pragma unroll
            for (int k = 0; k < 32; k += 4) {
                float4 m4 = *(const float4*)(mrow_s + k);       // Eb
                float4 v4 = *(const float4*)(s_va + kc + k);
                #pragma unroll
                for (int t = 0; t < TT; t++) {
                    float4 d4 = *(const float4*)(s_dp + t * 512 + kc + k);   // Ea
                    float r0v = fast_rcp(fmaf(d4.x, m4.x, 1.f));
                    float r1v = fast_rcp(fmaf(d4.y, m4.y, 1.f));
                    float r2v = fast_rcp(fmaf(d4.z, m4.z, 1.f));
                    float r3v = fast_rcp(fmaf(d4.w, m4.w, 1.f));
                    ep[t] = fmaf(v4.x, r0v, ep[t]);
                    ep[t] = fmaf(v4.y, r1v, ep[t]);
                    ep[t] = fmaf(v4.z, r2v, ep[t]);
                    ep[t] = fmaf(v4.w, r3v, ep[t]);
                }
            }
        }
    }

    // logits: e = -2 * acc  (+ const, cancels in softmax)
    #pragma unroll
    for (int i = 0; i < 2 * TT; i++) acc[i] = -2.f * acc[i];

    const int* mk = mask + b * SRC;
    const int s0 = myrow, s1 = 256 + myrow;
    const float NEG_INF = __int_as_float(0xff800000);
    const bool m0 = (mk[s0] != 0), m1 = (mk[s1] != 0);
    #pragma unroll
    for (int t = 0; t < TT; t++) {
        if (!m0) acc[t]      = NEG_INF;
        if (!m1) acc[TT + t] = NEG_INF;
    }

    float mx[TT];
    #pragma unroll
    for (int t = 0; t < TT; t++) {
        float m = fmaxf(acc[t], acc[TT + t]);
        #pragma unroll
        for (int o = 16; o; o >>= 1) m = fmaxf(m, __shfl_xor_sync(0xffffffffu, m, o));
        if (lane == 0) s_red[t * 8 + w] = m;
    }
    __syncthreads();
    #pragma unroll
    for (int t = 0; t < TT; t++) {
        float m = s_red[t * 8 + 0];
        #pragma unroll
        for (int i = 1; i < 8; i++) m = fmaxf(m, s_red[t * 8 + i]);
        mx[t] = m;
    }
    __syncthreads();

    float inv[TT];
    #pragma unroll
    for (int t = 0; t < TT; t++) {
        float p0 = __expf(acc[t]      - mx[t]);
        float p1 = __expf(acc[TT + t] - mx[t]);
        acc[t] = p0; acc[TT + t] = p1;
        float s = p0 + p1;
        #pragma unroll
        for (int o = 16; o; o >>= 1) s += __shfl_xor_sync(0xffffffffu, s, o);
        if (lane == 0) s_red[t * 8 + w] = s;
    }
    __syncthreads();
    #pragma unroll
    for (int t = 0; t < TT; t++) {
        float s = s_red[t * 8 + 0];
        #pragma unroll
        for (int i = 1; i < 8; i++) s += s_red[t * 8 + i];
        inv[t] = 1.f / s;
    }

    #pragma unroll
    for (int t = 0; t < TT; t++) {
        float* arow = g_a + (size_t)(b * TGT + t0 + t) * SRC;
        arow[s0] = acc[t]      * inv[t];
        arow[s1] = acc[TT + t] * inv[t];
    }
}

// ---------------------------------------------------------------------------
// Context GEMM: out[b] = g_a[b] (128 x 512) @ memory[b] (512 x 512)
// ---------------------------------------------------------------------------
__global__ void __launch_bounds__(256) context_kernel(
    const float* __restrict__ memory,
    float* __restrict__ out)
{
    __shared__ float As[64 * 32];
    __shared__ float Bs[32 * 32];

    const int cb  = blockIdx.x;
    const int tb  = blockIdx.y;
    const int b   = blockIdx.z;
    const int tid = threadIdx.x;
    const int col = tid & 31;
    const int tr0 = (tid >> 5) * 8;

    const float* Ab = g_a + (size_t)(b * TGT + tb * 64) * SRC;
    const float* Bb = memory + (size_t)b * SRC * ED + cb * 32;

    const int ar = tid >> 2;
    const int ac = (tid & 3) * 8;
    const int br = tid >> 3;
    const int bc = (tid & 7) * 4;

    float acc[8];
    #pragma unroll
    for (int i = 0; i < 8; i++) acc[i] = 0.f;

    for (int sc = 0; sc < SRC; sc += 32) {
        __syncthreads();
        *(float4*)(As + ar * 32 + ac)     = *(const float4*)(Ab + (size_t)ar * SRC + sc + ac);
        *(float4*)(As + ar * 32 + ac + 4) = *(const float4*)(Ab + (size_t)ar * SRC + sc + ac + 4);
        *(float4*)(Bs + br * 32 + bc)     = *(const float4*)(Bb + (size_t)(sc + br) * ED + bc);
        __syncthreads();

        #pragma unroll
        for (int s = 0; s < 32; s++) {
            float bv = Bs[s * 32 + col];
            #pragma unroll
            for (int i = 0; i < 8; i++)
                acc[i] = fmaf(As[(tr0 + i) * 32 + s], bv, acc[i]);
        }
    }

    #pragma unroll
    for (int i = 0; i < 8; i++)
        out[(size_t)(b * TGT + tb * 64 + tr0 + i) * ED + cb * 32 + col] = acc[i];
}

// ---------------------------------------------------------------------------
extern "C" void kernel_launch(void* const* d_in, const int* in_sizes, int n_in,
                              void* d_out, int out_size)
{
    const float* memory = (const float*)d_in[0];
    const float* dec    = (const float*)d_in[1];
    const int*   mask   = (const int*)d_in[2];
    const float* Wa     = (const float*)d_in[3];
    const float* Va     = (const float*)d_in[4];
    float*       out    = (float*)d_out;

    (void)in_sizes; (void)n_in; (void)out_size;

    conv_a<<<2560, 256>>>(memory, dec);
    conv_w<<<dim3(16, 16, 2), dim3(32, 8)>>>(Wa);
    gemm_tc<<<dim3(8, 40), 256>>>();
    score_kernel<<<dim3(TGT / TT, BB), 256>>>(Va, mask);
    context_kernel<<<dim3(16, 2, BB), 256>>>(memory, out);
}

// round 9
// speedup vs baseline: 1.1114x; 1.1114x over previous
#include <cuda_runtime.h>
#include <cuda_bf16.h>
#include <cstdint>

#define BB   8
#define SRC  512
#define TGT  128
#define ED   512
#define DD   512
#define TT   4

// Scratch (device globals: allocation-free per harness rules)
// NOTE: g_mp/g_dp hold Eb = exp(2*mp), Ea = exp(2*dp) (written by gemm_tc).
__device__ float g_mp[BB * SRC * DD];          // 8 MB
__device__ float g_dp[BB * TGT * DD];          // 2 MB
__device__ float g_a [BB * TGT * SRC];         // 2 MB: softmax probabilities
__device__ __nv_bfloat16 g_Ah[5120 * 512];     // A hi (memory rows 0..4095, dec 4096..5119)
__device__ __nv_bfloat16 g_Al[5120 * 512];     // A lo
__device__ __nv_bfloat16 g_Wth[2 * 512 * 512]; // W^T hi: sel 0 = Wa_d, 1 = Wa_m; [n][k]
__device__ __nv_bfloat16 g_Wtl[2 * 512 * 512]; // W^T lo

__device__ __forceinline__ float fast_rcp(float x) {
    float y;
    asm("rcp.approx.ftz.f32 %0, %1;" : "=f"(y) : "f"(x));   // .ftz -> bare MUFU.RCP
    return y;
}

__device__ __forceinline__ void cp_async16(void* smem_dst, const void* gmem_src) {
    uint32_t d = (uint32_t)__cvta_generic_to_shared(smem_dst);
    asm volatile("cp.async.ca.shared.global [%0], [%1], 16;\n" :: "r"(d), "l"(gmem_src));
}
#define CP_COMMIT() asm volatile("cp.async.commit_group;\n")
#define CP_WAIT1()  asm volatile("cp.async.wait_group 1;\n")
#define CP_WAIT0()  asm volatile("cp.async.wait_group 0;\n")

__device__ __forceinline__ void ldm_x4(uint32_t* r, uint32_t addr) {
    asm volatile("ldmatrix.sync.aligned.m8n8.x4.shared.b16 {%0,%1,%2,%3}, [%4];"
                 : "=r"(r[0]), "=r"(r[1]), "=r"(r[2]), "=r"(r[3]) : "r"(addr));
}
__device__ __forceinline__ void mma16816(float* c, const uint32_t* a, const uint32_t* b) {
    asm volatile("mma.sync.aligned.m16n8k16.row.col.f32.bf16.bf16.f32 "
                 "{%0,%1,%2,%3}, {%4,%5,%6,%7}, {%8,%9}, {%0,%1,%2,%3};"
                 : "+f"(c[0]), "+f"(c[1]), "+f"(c[2]), "+f"(c[3])
                 : "r"(a[0]), "r"(a[1]), "r"(a[2]), "r"(a[3]), "r"(b[0]), "r"(b[1]));
}

// ---------------------------------------------------------------------------
// Conversion: fp32 -> bf16 (hi, lo) for A = [memory ; dec]  (5120 x 512)
// ---------------------------------------------------------------------------
__global__ void __launch_bounds__(256) conv_a(
    const float* __restrict__ memory, const float* __restrict__ dec)
{
    const int idx = blockIdx.x * 256 + threadIdx.x;          // float4 index
    const float4 v = (idx < 524288) ? ((const float4*)memory)[idx]
                                    : ((const float4*)dec)[idx - 524288];
    float xs[4] = {v.x, v.y, v.z, v.w};
    __nv_bfloat16 h[4], l[4];
    #pragma unroll
    for (int i = 0; i < 4; i++) {
        h[i] = __float2bfloat16(xs[i]);
        l[i] = __float2bfloat16(xs[i] - __bfloat162float(h[i]));
    }
    ((__nv_bfloat162*)g_Ah)[idx * 2]     = __halves2bfloat162(h[0], h[1]);
    ((__nv_bfloat162*)g_Ah)[idx * 2 + 1] = __halves2bfloat162(h[2], h[3]);
    ((__nv_bfloat162*)g_Al)[idx * 2]     = __halves2bfloat162(l[0], l[1]);
    ((__nv_bfloat162*)g_Al)[idx * 2 + 1] = __halves2bfloat162(l[2], l[3]);
}

// ---------------------------------------------------------------------------
// Conversion: W^T hi/lo.  Wt[sel][n][k] = Wa[sel*512 + k][n];  sel 0=Wa_d, 1=Wa_m
// ---------------------------------------------------------------------------
__global__ void __launch_bounds__(256) conv_w(const float* __restrict__ Wa)
{
    __shared__ float s[32][33];
    const int tx = threadIdx.x, ty = threadIdx.y;            // 32 x 8
    const int bx = blockIdx.x, by = blockIdx.y, sel = blockIdx.z;

    #pragma unroll
    for (int j = 0; j < 32; j += 8)
        s[ty + j][tx] = Wa[(size_t)(sel * 512 + by * 32 + ty + j) * 512 + bx * 32 + tx];
    __syncthreads();

    #pragma unroll
    for (int j = 0; j < 32; j += 8) {
        const int n = bx * 32 + ty + j;
        const int k = by * 32 + tx;
        float x = s[tx][ty + j];
        __nv_bfloat16 h = __float2bfloat16(x);
        __nv_bfloat16 l = __float2bfloat16(x - __bfloat162float(h));
        const size_t o = (size_t)(sel * 512 + n) * 512 + k;
        g_Wth[o] = h;
        g_Wtl[o] = l;
    }
}

// ---------------------------------------------------------------------------
// Tensor-core projection GEMM via mma.sync (bf16 3-way split, fp32 accum).
// EPILOGUE: store exp(2*proj) so the score kernel can use
// tanh(a+b) = 1 - 2/(1 + e^{2a} e^{2b}).
// ---------------------------------------------------------------------------
#define PITCH 48
#define OA_H  0
#define OA_L  6144
#define OW_H  12288
#define OW_L  15360
#define BUFSZ 18432

__global__ void __launch_bounds__(256, 2) gemm_tc()
{
    __shared__ char sm[2 * BUFSZ];                // 36 KB
    const uint32_t sb = (uint32_t)__cvta_generic_to_shared(sm);

    const int tid  = threadIdx.x;
    const int lane = tid & 31;
    const int w    = tid >> 5;
    const int wm   = w >> 1;                      // 0..3 (m)
    const int wn   = w & 1;                       // 0..1 (n)
    const int bn   = blockIdx.x;                  // 0..7
    const int by   = blockIdx.y;                  // 0..39

    const int m_base = by * 128;
    const int sel    = (by < 32) ? 1 : 0;
    float* C = (by < 32) ? (g_mp + (size_t)by * 128 * 512)
                         : (g_dp + (size_t)(by - 32) * 128 * 512);
    const __nv_bfloat16* Wh = g_Wth + (size_t)sel * 512 * 512 + (size_t)bn * 64 * 512;
    const __nv_bfloat16* Wl = g_Wtl + (size_t)sel * 512 * 512 + (size_t)bn * 64 * 512;

    const int ar = tid >> 1, ac = tid & 1;
    const int wr = (tid & 127) >> 1, wc = tid & 1;
    const bool do_w = (tid < 128);

    auto issue = [&](int kc, int buf) {
        char* B = sm + buf * BUFSZ;
        const size_t asrc = (size_t)(m_base + ar) * 512 + kc * 16 + ac * 8;
        cp_async16(B + OA_H + ar * PITCH + ac * 16, g_Ah + asrc);
        cp_async16(B + OA_L + ar * PITCH + ac * 16, g_Al + asrc);
        if (do_w) {
            const size_t wsrc = (size_t)wr * 512 + kc * 16 + wc * 8;
            cp_async16(B + OW_H + wr * PITCH + wc * 16, Wh + wsrc);
            cp_async16(B + OW_L + wr * PITCH + wc * 16, Wl + wsrc);
        }
        CP_COMMIT();
    };

    const uint32_t a_off = (uint32_t)((wm * 32 + (lane & 15)) * PITCH + (lane >> 4) * 16);
    const uint32_t b_off = (uint32_t)((wn * 32 + (lane & 7) + ((lane >> 4) * 8)) * PITCH
                                      + (((lane >> 3) & 1) * 16));

    float acc[2][4][4];
    #pragma unroll
    for (int i = 0; i < 2; i++)
        #pragma unroll
        for (int j = 0; j < 4; j++)
            #pragma unroll
            for (int e = 0; e < 4; e++) acc[i][j][e] = 0.f;

    issue(0, 0);

    for (int kc = 0; kc < 32; kc++) {
        if (kc < 31) { issue(kc + 1, (kc + 1) & 1); CP_WAIT1(); }
        else         { CP_WAIT0(); }
        __syncthreads();

        const uint32_t base = sb + (kc & 1) * BUFSZ;
        uint32_t ah[2][4], al[2][4], bh[2][4], bl[2][4];
        #pragma unroll
        for (int i = 0; i < 2; i++) {
            ldm_x4(ah[i], base + OA_H + a_off + i * 16 * PITCH);
            ldm_x4(al[i], base + OA_L + a_off + i * 16 * PITCH);
        }
        #pragma unroll
        for (int j = 0; j < 2; j++) {
            ldm_x4(bh[j], base + OW_H + b_off + j * 16 * PITCH);
            ldm_x4(bl[j], base + OW_L + b_off + j * 16 * PITCH);
        }

        #pragma unroll
        for (int i = 0; i < 2; i++)
            #pragma unroll
            for (int j = 0; j < 4; j++) {
                const uint32_t* ph = &bh[j >> 1][2 * (j & 1)];
                const uint32_t* pl = &bl[j >> 1][2 * (j & 1)];
                mma16816(acc[i][j], ah[i], ph);
                mma16816(acc[i][j], ah[i], pl);
                mma16816(acc[i][j], al[i], ph);
            }
        __syncthreads();
    }

    // epilogue: store E = exp(2 * proj)
    #pragma unroll
    for (int i = 0; i < 2; i++) {
        const int r0 = wm * 32 + i * 16 + (lane >> 2);
        #pragma unroll
        for (int j = 0; j < 4; j++) {
            const int c0 = bn * 64 + wn * 32 + j * 8 + (lane & 3) * 2;
            *(float2*)(C + (size_t)r0 * 512 + c0) =
                make_float2(__expf(2.f * acc[i][j][0]), __expf(2.f * acc[i][j][1]));
            *(float2*)(C + (size_t)(r0 + 8) * 512 + c0) =
                make_float2(__expf(2.f * acc[i][j][2]), __expf(2.f * acc[i][j][3]));
        }
    }
}

// ---------------------------------------------------------------------------
// Score + masked softmax -> g_a.
// e[t,s] = const - 2 * sum_k Va_k / (1 + Ea[t,k]*Eb[s,k]); const cancels in
// softmax. Inner element: 1 FMA (den) + 1 MUFU.RCP (rt=8) + 1 FMA (acc).
// Layout identical to measured-best R4: 8 warps, TT=4 t/block, 256-row tile.
// ---------------------------------------------------------------------------
__global__ void __launch_bounds__(256, 4) score_kernel(
    const float* __restrict__ Va,
    const int* __restrict__ mask)
{
    __shared__ float s_mp[256 * 36];
    __shared__ float s_dp[TT * 512];
    __shared__ float s_va[512];
    __shared__ float s_red[TT * 8];

    const int b    = blockIdx.y;
    const int t0   = blockIdx.x * TT;
    const int tid  = threadIdx.x;
    const int lane = tid & 31;
    const int w    = tid >> 5;

    {
        const float4* dpg = (const float4*)(g_dp + (size_t)(b * TGT + t0) * 512);
        ((float4*)s_dp)[tid]       = dpg[tid];
        ((float4*)s_dp)[tid + 256] = dpg[tid + 256];
        if (tid < 128) ((float4*)s_va)[tid] = ((const float4*)Va)[tid];
    }

    float acc[2 * TT];
    #pragma unroll
    for (int i = 0; i < 2 * TT; i++) acc[i] = 0.f;

    const int r0    = tid >> 3;
    const int c4    = (tid & 7) << 2;
    const int myrow = w * 32 + lane;

    #pragma unroll
    for (int stage = 0; stage < 2; stage++) {
        const float* mpg = g_mp + (size_t)(b * SRC + stage * 256) * 512;
        float* ep = acc + stage * TT;
        for (int kc = 0; kc < 512; kc += 32) {
            __syncthreads();
            #pragma unroll
            for (int rr = 0; rr < 256; rr += 32) {
                float4 v = *(const float4*)(mpg + (size_t)(r0 + rr) * 512 + kc + c4);
                *(float4*)(s_mp + (r0 + rr) * 36 + c4) = v;
            }
            __syncthreads();

            const float* mrow_s = s_mp + myrow * 36;
            #pragma unroll
            for (int k = 0; k < 32; k += 4) {
                float4 m4 = *(const float4*)(mrow_s + k);       // Eb
                float4 v4 = *(const float4*)(s_va + kc + k);
                #pragma unroll
                for (int t = 0; t < TT; t++) {
                    float4 d4 = *(const float4*)(s_dp + t * 512 + kc + k);   // Ea
                    float r0v = fast_rcp(fmaf(d4.x, m4.x, 1.f));
                    float r1v = fast_rcp(fmaf(d4.y, m4.y, 1.f));
                    float r2v = fast_rcp(fmaf(d4.z, m4.z, 1.f));
                    float r3v = fast_rcp(fmaf(d4.w, m4.w, 1.f));
                    ep[t] = fmaf(v4.x, r0v, ep[t]);
                    ep[t] = fmaf(v4.y, r1v, ep[t]);
                    ep[t] = fmaf(v4.z, r2v, ep[t]);
                    ep[t] = fmaf(v4.w, r3v, ep[t]);
                }
            }
        }
    }

    // logits: e = -2 * acc  (+ const, cancels in softmax)
    #pragma unroll
    for (int i = 0; i < 2 * TT; i++) acc[i] = -2.f * acc[i];

    const int* mk = mask + b * SRC;
    const int s0 = myrow, s1 = 256 + myrow;
    const float NEG_INF = __int_as_float(0xff800000);
    const bool m0 = (mk[s0] != 0), m1 = (mk[s1] != 0);
    #pragma unroll
    for (int t = 0; t < TT; t++) {
        if (!m0) acc[t]      = NEG_INF;
        if (!m1) acc[TT + t] = NEG_INF;
    }

    float mx[TT];
    #pragma unroll
    for (int t = 0; t < TT; t++) {
        float m = fmaxf(acc[t], acc[TT + t]);
        #pragma unroll
        for (int o = 16; o; o >>= 1) m = fmaxf(m, __shfl_xor_sync(0xffffffffu, m, o));
        if (lane == 0) s_red[t * 8 + w] = m;
    }
    __syncthreads();
    #pragma unroll
    for (int t = 0; t < TT; t++) {
        float m = s_red[t * 8 + 0];
        #pragma unroll
        for (int i = 1; i < 8; i++) m = fmaxf(m, s_red[t * 8 + i]);
        mx[t] = m;
    }
    __syncthreads();

    float inv[TT];
    #pragma unroll
    for (int t = 0; t < TT; t++) {
        float p0 = __expf(acc[t]      - mx[t]);
        float p1 = __expf(acc[TT + t] - mx[t]);
        acc[t] = p0; acc[TT + t] = p1;
        float s = p0 + p1;
        #pragma unroll
        for (int o = 16; o; o >>= 1) s += __shfl_xor_sync(0xffffffffu, s, o);
        if (lane == 0) s_red[t * 8 + w] = s;
    }
    __syncthreads();
    #pragma unroll
    for (int t = 0; t < TT; t++) {
        float s = s_red[t * 8 + 0];
        #pragma unroll
        for (int i = 1; i < 8; i++) s += s_red[t * 8 + i];
        inv[t] = 1.f / s;
    }

    #pragma unroll
    for (int t = 0; t < TT; t++) {
        float* arow = g_a + (size_t)(b * TGT + t0 + t) * SRC;
        arow[s0] = acc[t]      * inv[t];
        arow[s1] = acc[TT + t] * inv[t];
    }
}

// ---------------------------------------------------------------------------
// Context GEMM: out[b] = g_a[b] (128 x 512) @ memory[b] (512 x 512)
// ---------------------------------------------------------------------------
__global__ void __launch_bounds__(256) context_kernel(
    const float* __restrict__ memory,
    float* __restrict__ out)
{
    __shared__ float As[64 * 32];
    __shared__ float Bs[32 * 32];

    const int cb  = blockIdx.x;
    const int tb  = blockIdx.y;
    const int b   = blockIdx.z;
    const int tid = threadIdx.x;
    const int col = tid & 31;
    const int tr0 = (tid >> 5) * 8;

    const float* Ab = g_a + (size_t)(b * TGT + tb * 64) * SRC;
    const float* Bb = memory + (size_t)b * SRC * ED + cb * 32;

    const int ar = tid >> 2;
    const int ac = (tid & 3) * 8;
    const int br = tid >> 3;
    const int bc = (tid & 7) * 4;

    float acc[8];
    #pragma unroll
    for (int i = 0; i < 8; i++) acc[i] = 0.f;

    for (int sc = 0; sc < SRC; sc += 32) {
        __syncthreads();
        *(float4*)(As + ar * 32 + ac)     = *(const float4*)(Ab + (size_t)ar * SRC + sc + ac);
        *(float4*)(As + ar * 32 + ac + 4) = *(const float4*)(Ab + (size_t)ar * SRC + sc + ac + 4);
        *(float4*)(Bs + br * 32 + bc)     = *(const float4*)(Bb + (size_t)(sc + br) * ED + bc);
        __syncthreads();

        #pragma unroll
        for (int s = 0; s < 32; s++) {
            float bv = Bs[s * 32 + col];
            #pragma unroll
            for (int i = 0; i < 8; i++)
                acc[i] = fmaf(As[(tr0 + i) * 32 + s], bv, acc[i]);
        }
    }

    #pragma unroll
    for (int i = 0; i < 8; i++)
        out[(size_t)(b * TGT + tb * 64 + tr0 + i) * ED + cb * 32 + col] = acc[i];
}

// ---------------------------------------------------------------------------
extern "C" void kernel_launch(void* const* d_in, const int* in_sizes, int n_in,
                              void* d_out, int out_size)
{
    const float* memory = (const float*)d_in[0];
    const float* dec    = (const float*)d_in[1];
    const int*   mask   = (const int*)d_in[2];
    const float* Wa     = (const float*)d_in[3];
    const float* Va     = (const float*)d_in[4];
    float*       out    = (float*)d_out;

    (void)in_sizes; (void)n_in; (void)out_size;

    conv_a<<<2560, 256>>>(memory, dec);
    conv_w<<<dim3(16, 16, 2), dim3(32, 8)>>>(Wa);
    gemm_tc<<<dim3(8, 40), 256>>>();
    score_kernel<<<dim3(TGT / TT, BB), 256>>>(Va, mask);
    context_kernel<<<dim3(16, 2, BB), 256>>>(memory, out);
}

// round 10
// speedup vs baseline: 1.1924x; 1.0729x over previous
#include <cuda_runtime.h>
#include <cuda_bf16.h>
#include <cstdint>

#define BB   8
#define SRC  512
#define TGT  128
#define ED   512
#define DD   512
#define TT   4

// Scratch (device globals: allocation-free per harness rules)
// NOTE: g_mp/g_dp hold Eb = exp(2*mp), Ea = exp(2*dp) (written by gemm_tc).
__device__ float g_mp[BB * SRC * DD];          // 8 MB
__device__ float g_dp[BB * TGT * DD];          // 2 MB
__device__ float g_a [BB * TGT * SRC];         // 2 MB: UNNORMALIZED exp(logit)
__device__ float g_psum[BB * TGT * 2];         // per-(b,t,s-half) partial sums
__device__ __nv_bfloat16 g_Ah[5120 * 512];     // A hi (memory rows 0..4095, dec 4096..5119)
__device__ __nv_bfloat16 g_Al[5120 * 512];     // A lo
__device__ __nv_bfloat16 g_Wth[2 * 512 * 512]; // W^T hi: sel 0 = Wa_d, 1 = Wa_m; [n][k]
__device__ __nv_bfloat16 g_Wtl[2 * 512 * 512]; // W^T lo

__device__ __forceinline__ float fast_rcp(float x) {
    float y;
    asm("rcp.approx.ftz.f32 %0, %1;" : "=f"(y) : "f"(x));   // bare MUFU.RCP
    return y;
}

__device__ __forceinline__ void cp_async16(void* smem_dst, const void* gmem_src) {
    uint32_t d = (uint32_t)__cvta_generic_to_shared(smem_dst);
    asm volatile("cp.async.ca.shared.global [%0], [%1], 16;\n" :: "r"(d), "l"(gmem_src));
}
#define CP_COMMIT() asm volatile("cp.async.commit_group;\n")
#define CP_WAIT1()  asm volatile("cp.async.wait_group 1;\n")
#define CP_WAIT0()  asm volatile("cp.async.wait_group 0;\n")

__device__ __forceinline__ void ldm_x4(uint32_t* r, uint32_t addr) {
    asm volatile("ldmatrix.sync.aligned.m8n8.x4.shared.b16 {%0,%1,%2,%3}, [%4];"
                 : "=r"(r[0]), "=r"(r[1]), "=r"(r[2]), "=r"(r[3]) : "r"(addr));
}
__device__ __forceinline__ void mma16816(float* c, const uint32_t* a, const uint32_t* b) {
    asm volatile("mma.sync.aligned.m16n8k16.row.col.f32.bf16.bf16.f32 "
                 "{%0,%1,%2,%3}, {%4,%5,%6,%7}, {%8,%9}, {%0,%1,%2,%3};"
                 : "+f"(c[0]), "+f"(c[1]), "+f"(c[2]), "+f"(c[3])
                 : "r"(a[0]), "r"(a[1]), "r"(a[2]), "r"(a[3]), "r"(b[0]), "r"(b[1]));
}

// ---------------------------------------------------------------------------
// Conversion: fp32 -> bf16 (hi, lo) for A = [memory ; dec]  (5120 x 512)
// ---------------------------------------------------------------------------
__global__ void __launch_bounds__(256) conv_a(
    const float* __restrict__ memory, const float* __restrict__ dec)
{
    const int idx = blockIdx.x * 256 + threadIdx.x;          // float4 index
    const float4 v = (idx < 524288) ? ((const float4*)memory)[idx]
                                    : ((const float4*)dec)[idx - 524288];
    float xs[4] = {v.x, v.y, v.z, v.w};
    __nv_bfloat16 h[4], l[4];
    #pragma unroll
    for (int i = 0; i < 4; i++) {
        h[i] = __float2bfloat16(xs[i]);
        l[i] = __float2bfloat16(xs[i] - __bfloat162float(h[i]));
    }
    ((__nv_bfloat162*)g_Ah)[idx * 2]     = __halves2bfloat162(h[0], h[1]);
    ((__nv_bfloat162*)g_Ah)[idx * 2 + 1] = __halves2bfloat162(h[2], h[3]);
    ((__nv_bfloat162*)g_Al)[idx * 2]     = __halves2bfloat162(l[0], l[1]);
    ((__nv_bfloat162*)g_Al)[idx * 2 + 1] = __halves2bfloat162(l[2], l[3]);
}

// ---------------------------------------------------------------------------
// Conversion: W^T hi/lo.  Wt[sel][n][k] = Wa[sel*512 + k][n];  sel 0=Wa_d, 1=Wa_m
// ---------------------------------------------------------------------------
__global__ void __launch_bounds__(256) conv_w(const float* __restrict__ Wa)
{
    __shared__ float s[32][33];
    const int tx = threadIdx.x, ty = threadIdx.y;            // 32 x 8
    const int bx = blockIdx.x, by = blockIdx.y, sel = blockIdx.z;

    #pragma unroll
    for (int j = 0; j < 32; j += 8)
        s[ty + j][tx] = Wa[(size_t)(sel * 512 + by * 32 + ty + j) * 512 + bx * 32 + tx];
    __syncthreads();

    #pragma unroll
    for (int j = 0; j < 32; j += 8) {
        const int n = bx * 32 + ty + j;
        const int k = by * 32 + tx;
        float x = s[tx][ty + j];
        __nv_bfloat16 h = __float2bfloat16(x);
        __nv_bfloat16 l = __float2bfloat16(x - __bfloat162float(h));
        const size_t o = (size_t)(sel * 512 + n) * 512 + k;
        g_Wth[o] = h;
        g_Wtl[o] = l;
    }
}

// ---------------------------------------------------------------------------
// Tensor-core projection GEMM via mma.sync (bf16 3-way split, fp32 accum).
// EPILOGUE: store exp(2*proj) so the score kernel can use
// tanh(a+b) = 1 - 2/(1 + e^{2a} e^{2b}).
// ---------------------------------------------------------------------------
#define PITCH 48
#define OA_H  0
#define OA_L  6144
#define OW_H  12288
#define OW_L  15360
#define BUFSZ 18432

__global__ void __launch_bounds__(256, 2) gemm_tc()
{
    __shared__ char sm[2 * BUFSZ];                // 36 KB
    const uint32_t sb = (uint32_t)__cvta_generic_to_shared(sm);

    const int tid  = threadIdx.x;
    const int lane = tid & 31;
    const int w    = tid >> 5;
    const int wm   = w >> 1;
    const int wn   = w & 1;
    const int bn   = blockIdx.x;
    const int by   = blockIdx.y;

    const int m_base = by * 128;
    const int sel    = (by < 32) ? 1 : 0;
    float* C = (by < 32) ? (g_mp + (size_t)by * 128 * 512)
                         : (g_dp + (size_t)(by - 32) * 128 * 512);
    const __nv_bfloat16* Wh = g_Wth + (size_t)sel * 512 * 512 + (size_t)bn * 64 * 512;
    const __nv_bfloat16* Wl = g_Wtl + (size_t)sel * 512 * 512 + (size_t)bn * 64 * 512;

    const int ar = tid >> 1, ac = tid & 1;
    const int wr = (tid & 127) >> 1, wc = tid & 1;
    const bool do_w = (tid < 128);

    auto issue = [&](int kc, int buf) {
        char* B = sm + buf * BUFSZ;
        const size_t asrc = (size_t)(m_base + ar) * 512 + kc * 16 + ac * 8;
        cp_async16(B + OA_H + ar * PITCH + ac * 16, g_Ah + asrc);
        cp_async16(B + OA_L + ar * PITCH + ac * 16, g_Al + asrc);
        if (do_w) {
            const size_t wsrc = (size_t)wr * 512 + kc * 16 + wc * 8;
            cp_async16(B + OW_H + wr * PITCH + wc * 16, Wh + wsrc);
            cp_async16(B + OW_L + wr * PITCH + wc * 16, Wl + wsrc);
        }
        CP_COMMIT();
    };

    const uint32_t a_off = (uint32_t)((wm * 32 + (lane & 15)) * PITCH + (lane >> 4) * 16);
    const uint32_t b_off = (uint32_t)((wn * 32 + (lane & 7) + ((lane >> 4) * 8)) * PITCH
                                      + (((lane >> 3) & 1) * 16));

    float acc[2][4][4];
    #pragma unroll
    for (int i = 0; i < 2; i++)
        #pragma unroll
        for (int j = 0; j < 4; j++)
            #pragma unroll
            for (int e = 0; e < 4; e++) acc[i][j][e] = 0.f;

    issue(0, 0);

    for (int kc = 0; kc < 32; kc++) {
        if (kc < 31) { issue(kc + 1, (kc + 1) & 1); CP_WAIT1(); }
        else         { CP_WAIT0(); }
        __syncthreads();

        const uint32_t base = sb + (kc & 1) * BUFSZ;
        uint32_t ah[2][4], al[2][4], bh[2][4], bl[2][4];
        #pragma unroll
        for (int i = 0; i < 2; i++) {
            ldm_x4(ah[i], base + OA_H + a_off + i * 16 * PITCH);
            ldm_x4(al[i], base + OA_L + a_off + i * 16 * PITCH);
        }
        #pragma unroll
        for (int j = 0; j < 2; j++) {
            ldm_x4(bh[j], base + OW_H + b_off + j * 16 * PITCH);
            ldm_x4(bl[j], base + OW_L + b_off + j * 16 * PITCH);
        }

        #pragma unroll
        for (int i = 0; i < 2; i++)
            #pragma unroll
            for (int j = 0; j < 4; j++) {
                const uint32_t* ph = &bh[j >> 1][2 * (j & 1)];
                const uint32_t* pl = &bl[j >> 1][2 * (j & 1)];
                mma16816(acc[i][j], ah[i], ph);
                mma16816(acc[i][j], ah[i], pl);
                mma16816(acc[i][j], al[i], ph);
            }
        __syncthreads();
    }

    // epilogue: store E = exp(2 * proj)
    #pragma unroll
    for (int i = 0; i < 2; i++) {
        const int r0 = wm * 32 + i * 16 + (lane >> 2);
        #pragma unroll
        for (int j = 0; j < 4; j++) {
            const int c0 = bn * 64 + wn * 32 + j * 8 + (lane & 3) * 2;
            *(float2*)(C + (size_t)r0 * 512 + c0) =
                make_float2(__expf(2.f * acc[i][j][0]), __expf(2.f * acc[i][j][1]));
            *(float2*)(C + (size_t)(r0 + 8) * 512 + c0) =
                make_float2(__expf(2.f * acc[i][j][2]), __expf(2.f * acc[i][j][3]));
        }
    }
}

// ---------------------------------------------------------------------------
// Score -> unnormalized p = exp(e) in g_a + per-half partial sums in g_psum.
// e[t,s] = -2 * sum_k Va_k / (1 + Ea[t,k]*Eb[s,k])  (+const, cancels; bounded
// |e| <= 2*sum|Va| ~ 36 -> exp safe in fp32, no max pass needed).
// Grid (TGT/TT, 2 s-halves, BB) = 512 blocks -> ~3.5 blocks/SM (occ ~43%).
// Block: TT=4 t, 256 s-rows (its half); warp w owns rows w*32+lane.
// ---------------------------------------------------------------------------
__global__ void __launch_bounds__(256, 4) score_kernel(
    const float* __restrict__ Va,
    const int* __restrict__ mask)
{
    __shared__ float s_mp[256 * 36];    // 36 KB
    __shared__ float s_dp[TT * 512];    //  8 KB
    __shared__ float s_va[512];         //  2 KB
    __shared__ float s_red[TT * 8];

    const int b    = blockIdx.z;
    const int half = blockIdx.y;
    const int t0   = blockIdx.x * TT;
    const int tid  = threadIdx.x;
    const int lane = tid & 31;
    const int w    = tid >> 5;

    {
        const float4* dpg = (const float4*)(g_dp + (size_t)(b * TGT + t0) * 512);
        ((float4*)s_dp)[tid]       = dpg[tid];
        ((float4*)s_dp)[tid + 256] = dpg[tid + 256];
        if (tid < 128) ((float4*)s_va)[tid] = ((const float4*)Va)[tid];
    }

    float acc[TT];
    #pragma unroll
    for (int i = 0; i < TT; i++) acc[i] = 0.f;

    const int r0    = tid >> 3;
    const int c4    = (tid & 7) << 2;
    const int myrow = w * 32 + lane;

    const float* mpg = g_mp + (size_t)(b * SRC + half * 256) * 512;
    for (int kc = 0; kc < 512; kc += 32) {
        __syncthreads();
        #pragma unroll
        for (int rr = 0; rr < 256; rr += 32) {
            float4 v = *(const float4*)(mpg + (size_t)(r0 + rr) * 512 + kc + c4);
            *(float4*)(s_mp + (r0 + rr) * 36 + c4) = v;
        }
        __syncthreads();

        const float* mrow_s = s_mp + myrow * 36;
        #pragma unroll
        for (int k = 0; k < 32; k += 4) {
            float4 m4 = *(const float4*)(mrow_s + k);       // Eb
            float4 v4 = *(const float4*)(s_va + kc + k);
            #pragma unroll
            for (int t = 0; t < TT; t++) {
                float4 d4 = *(const float4*)(s_dp + t * 512 + kc + k);   // Ea
                float r0v = fast_rcp(fmaf(d4.x, m4.x, 1.f));
                float r1v = fast_rcp(fmaf(d4.y, m4.y, 1.f));
                float r2v = fast_rcp(fmaf(d4.z, m4.z, 1.f));
                float r3v = fast_rcp(fmaf(d4.w, m4.w, 1.f));
                acc[t] = fmaf(v4.x, r0v, acc[t]);
                acc[t] = fmaf(v4.y, r1v, acc[t]);
                acc[t] = fmaf(v4.z, r2v, acc[t]);
                acc[t] = fmaf(v4.w, r3v, acc[t]);
            }
        }
    }

    // p = exp(-2*acc), masked to 0
    const int sg = half * 256 + myrow;
    const bool mok = (mask[b * SRC + sg] != 0);
    float p[TT];
    #pragma unroll
    for (int t = 0; t < TT; t++)
        p[t] = mok ? __expf(-2.f * acc[t]) : 0.f;

    // partial sums per t over this block's 256 s
    #pragma unroll
    for (int t = 0; t < TT; t++) {
        float s = p[t];
        #pragma unroll
        for (int o = 16; o; o >>= 1) s += __shfl_xor_sync(0xffffffffu, s, o);
        if (lane == 0) s_red[t * 8 + w] = s;
    }
    __syncthreads();
    if (tid < TT) {
        float s = s_red[tid * 8 + 0];
        #pragma unroll
        for (int i = 1; i < 8; i++) s += s_red[tid * 8 + i];
        g_psum[(b * TGT + t0 + tid) * 2 + half] = s;
    }

    #pragma unroll
    for (int t = 0; t < TT; t++)
        g_a[(size_t)(b * TGT + t0 + t) * SRC + sg] = p[t];
}

// ---------------------------------------------------------------------------
// Context GEMM + normalization:
// out[b,t,:] = (g_a[b,t,:] @ memory[b]) / (psum[b,t,0] + psum[b,t,1])
// ---------------------------------------------------------------------------
__global__ void __launch_bounds__(256) context_kernel(
    const float* __restrict__ memory,
    float* __restrict__ out)
{
    __shared__ float As[64 * 32];
    __shared__ float Bs[32 * 32];

    const int cb  = blockIdx.x;
    const int tb  = blockIdx.y;
    const int b   = blockIdx.z;
    const int tid = threadIdx.x;
    const int col = tid & 31;
    const int tr0 = (tid >> 5) * 8;

    const float* Ab = g_a + (size_t)(b * TGT + tb * 64) * SRC;
    const float* Bb = memory + (size_t)b * SRC * ED + cb * 32;

    const int ar = tid >> 2;
    const int ac = (tid & 3) * 8;
    const int br = tid >> 3;
    const int bc = (tid & 7) * 4;

    float acc[8];
    #pragma unroll
    for (int i = 0; i < 8; i++) acc[i] = 0.f;

    for (int sc = 0; sc < SRC; sc += 32) {
        __syncthreads();
        *(float4*)(As + ar * 32 + ac)     = *(const float4*)(Ab + (size_t)ar * SRC + sc + ac);
        *(float4*)(As + ar * 32 + ac + 4) = *(const float4*)(Ab + (size_t)ar * SRC + sc + ac + 4);
        *(float4*)(Bs + br * 32 + bc)     = *(const float4*)(Bb + (size_t)(sc + br) * ED + bc);
        __syncthreads();

        #pragma unroll
        for (int s = 0; s < 32; s++) {
            float bv = Bs[s * 32 + col];
            #pragma unroll
            for (int i = 0; i < 8; i++)
                acc[i] = fmaf(As[(tr0 + i) * 32 + s], bv, acc[i]);
        }
    }

    #pragma unroll
    for (int i = 0; i < 8; i++) {
        const int t = tb * 64 + tr0 + i;
        const float inv = 1.f / (g_psum[(b * TGT + t) * 2] + g_psum[(b * TGT + t) * 2 + 1]);
        out[(size_t)(b * TGT + t) * ED + cb * 32 + col] = acc[i] * inv;
    }
}

// ---------------------------------------------------------------------------
extern "C" void kernel_launch(void* const* d_in, const int* in_sizes, int n_in,
                              void* d_out, int out_size)
{
    const float* memory = (const float*)d_in[0];
    const float* dec    = (const float*)d_in[1];
    const int*   mask   = (const int*)d_in[2];
    const float* Wa     = (const float*)d_in[3];
    const float* Va     = (const float*)d_in[4];
    float*       out    = (float*)d_out;

    (void)in_sizes; (void)n_in; (void)out_size;

    conv_a<<<2560, 256>>>(memory, dec);
    conv_w<<<dim3(16, 16, 2), dim3(32, 8)>>>(Wa);
    gemm_tc<<<dim3(8, 40), 256>>>();
    score_kernel<<<dim3(TGT / TT, 2, BB), 256>>>(Va, mask);
    context_kernel<<<dim3(16, 2, BB), 256>>>(memory, out);
}

// round 11
// speedup vs baseline: 1.2676x; 1.0630x over previous
#include <cuda_runtime.h>
#include <cuda_bf16.h>
#include <cstdint>

#define BB   8
#define SRC  512
#define TGT  128
#define ED   512
#define DD   512
#define TT   4

// Scratch (device globals: allocation-free per harness rules)
// NOTE: g_mp/g_dp hold Eb = exp(2*mp), Ea = exp(2*dp) (written by gemm_tc).
__device__ float g_mp[BB * SRC * DD];          // 8 MB
__device__ float g_dp[BB * TGT * DD];          // 2 MB
__device__ float g_a [BB * TGT * SRC];         // 2 MB: UNNORMALIZED exp(logit)
__device__ float g_psum[BB * TGT * 4];         // per-(b,t,s-quarter) partial sums
__device__ __nv_bfloat16 g_Ah[5120 * 512];     // A hi (memory rows 0..4095, dec 4096..5119)
__device__ __nv_bfloat16 g_Al[5120 * 512];     // A lo
__device__ __nv_bfloat16 g_Wth[2 * 512 * 512]; // W^T hi: sel 0 = Wa_d, 1 = Wa_m; [n][k]
__device__ __nv_bfloat16 g_Wtl[2 * 512 * 512]; // W^T lo

__device__ __forceinline__ float fast_rcp(float x) {
    float y;
    asm("rcp.approx.ftz.f32 %0, %1;" : "=f"(y) : "f"(x));   // bare MUFU.RCP
    return y;
}

__device__ __forceinline__ void cp_async16(void* smem_dst, const void* gmem_src) {
    uint32_t d = (uint32_t)__cvta_generic_to_shared(smem_dst);
    asm volatile("cp.async.ca.shared.global [%0], [%1], 16;\n" :: "r"(d), "l"(gmem_src));
}
#define CP_COMMIT() asm volatile("cp.async.commit_group;\n")
#define CP_WAIT1()  asm volatile("cp.async.wait_group 1;\n")
#define CP_WAIT0()  asm volatile("cp.async.wait_group 0;\n")

__device__ __forceinline__ void ldm_x4(uint32_t* r, uint32_t addr) {
    asm volatile("ldmatrix.sync.aligned.m8n8.x4.shared.b16 {%0,%1,%2,%3}, [%4];"
                 : "=r"(r[0]), "=r"(r[1]), "=r"(r[2]), "=r"(r[3]) : "r"(addr));
}
__device__ __forceinline__ void mma16816(float* c, const uint32_t* a, const uint32_t* b) {
    asm volatile("mma.sync.aligned.m16n8k16.row.col.f32.bf16.bf16.f32 "
                 "{%0,%1,%2,%3}, {%4,%5,%6,%7}, {%8,%9}, {%0,%1,%2,%3};"
                 : "+f"(c[0]), "+f"(c[1]), "+f"(c[2]), "+f"(c[3])
                 : "r"(a[0]), "r"(a[1]), "r"(a[2]), "r"(a[3]), "r"(b[0]), "r"(b[1]));
}

// ---------------------------------------------------------------------------
// Conversion: fp32 -> bf16 (hi, lo) for A = [memory ; dec]  (5120 x 512)
// ---------------------------------------------------------------------------
__global__ void __launch_bounds__(256) conv_a(
    const float* __restrict__ memory, const float* __restrict__ dec)
{
    const int idx = blockIdx.x * 256 + threadIdx.x;          // float4 index
    const float4 v = (idx < 524288) ? ((const float4*)memory)[idx]
                                    : ((const float4*)dec)[idx - 524288];
    float xs[4] = {v.x, v.y, v.z, v.w};
    __nv_bfloat16 h[4], l[4];
    #pragma unroll
    for (int i = 0; i < 4; i++) {
        h[i] = __float2bfloat16(xs[i]);
        l[i] = __float2bfloat16(xs[i] - __bfloat162float(h[i]));
    }
    ((__nv_bfloat162*)g_Ah)[idx * 2]     = __halves2bfloat162(h[0], h[1]);
    ((__nv_bfloat162*)g_Ah)[idx * 2 + 1] = __halves2bfloat162(h[2], h[3]);
    ((__nv_bfloat162*)g_Al)[idx * 2]     = __halves2bfloat162(l[0], l[1]);
    ((__nv_bfloat162*)g_Al)[idx * 2 + 1] = __halves2bfloat162(l[2], l[3]);
}

// ---------------------------------------------------------------------------
// Conversion: W^T hi/lo.  Wt[sel][n][k] = Wa[sel*512 + k][n];  sel 0=Wa_d, 1=Wa_m
// ---------------------------------------------------------------------------
__global__ void __launch_bounds__(256) conv_w(const float* __restrict__ Wa)
{
    __shared__ float s[32][33];
    const int tx = threadIdx.x, ty = threadIdx.y;            // 32 x 8
    const int bx = blockIdx.x, by = blockIdx.y, sel = blockIdx.z;

    #pragma unroll
    for (int j = 0; j < 32; j += 8)
        s[ty + j][tx] = Wa[(size_t)(sel * 512 + by * 32 + ty + j) * 512 + bx * 32 + tx];
    __syncthreads();

    #pragma unroll
    for (int j = 0; j < 32; j += 8) {
        const int n = bx * 32 + ty + j;
        const int k = by * 32 + tx;
        float x = s[tx][ty + j];
        __nv_bfloat16 h = __float2bfloat16(x);
        __nv_bfloat16 l = __float2bfloat16(x - __bfloat162float(h));
        const size_t o = (size_t)(sel * 512 + n) * 512 + k;
        g_Wth[o] = h;
        g_Wtl[o] = l;
    }
}

// ---------------------------------------------------------------------------
// Tensor-core projection GEMM via mma.sync (bf16 3-way split, fp32 accum).
// EPILOGUE: store exp(2*proj) so the score kernel can use
// tanh(a+b) = 1 - 2/(1 + e^{2a} e^{2b}).
// ---------------------------------------------------------------------------
#define PITCH 48
#define OA_H  0
#define OA_L  6144
#define OW_H  12288
#define OW_L  15360
#define BUFSZ 18432

__global__ void __launch_bounds__(256, 2) gemm_tc()
{
    __shared__ char sm[2 * BUFSZ];                // 36 KB
    const uint32_t sb = (uint32_t)__cvta_generic_to_shared(sm);

    const int tid  = threadIdx.x;
    const int lane = tid & 31;
    const int w    = tid >> 5;
    const int wm   = w >> 1;
    const int wn   = w & 1;
    const int bn   = blockIdx.x;
    const int by   = blockIdx.y;

    const int m_base = by * 128;
    const int sel    = (by < 32) ? 1 : 0;
    float* C = (by < 32) ? (g_mp + (size_t)by * 128 * 512)
                         : (g_dp + (size_t)(by - 32) * 128 * 512);
    const __nv_bfloat16* Wh = g_Wth + (size_t)sel * 512 * 512 + (size_t)bn * 64 * 512;
    const __nv_bfloat16* Wl = g_Wtl + (size_t)sel * 512 * 512 + (size_t)bn * 64 * 512;

    const int ar = tid >> 1, ac = tid & 1;
    const int wr = (tid & 127) >> 1, wc = tid & 1;
    const bool do_w = (tid < 128);

    auto issue = [&](int kc, int buf) {
        char* B = sm + buf * BUFSZ;
        const size_t asrc = (size_t)(m_base + ar) * 512 + kc * 16 + ac * 8;
        cp_async16(B + OA_H + ar * PITCH + ac * 16, g_Ah + asrc);
        cp_async16(B + OA_L + ar * PITCH + ac * 16, g_Al + asrc);
        if (do_w) {
            const size_t wsrc = (size_t)wr * 512 + kc * 16 + wc * 8;
            cp_async16(B + OW_H + wr * PITCH + wc * 16, Wh + wsrc);
            cp_async16(B + OW_L + wr * PITCH + wc * 16, Wl + wsrc);
        }
        CP_COMMIT();
    };

    const uint32_t a_off = (uint32_t)((wm * 32 + (lane & 15)) * PITCH + (lane >> 4) * 16);
    const uint32_t b_off = (uint32_t)((wn * 32 + (lane & 7) + ((lane >> 4) * 8)) * PITCH
                                      + (((lane >> 3) & 1) * 16));

    float acc[2][4][4];
    #pragma unroll
    for (int i = 0; i < 2; i++)
        #pragma unroll
        for (int j = 0; j < 4; j++)
            #pragma unroll
            for (int e = 0; e < 4; e++) acc[i][j][e] = 0.f;

    issue(0, 0);

    for (int kc = 0; kc < 32; kc++) {
        if (kc < 31) { issue(kc + 1, (kc + 1) & 1); CP_WAIT1(); }
        else         { CP_WAIT0(); }
        __syncthreads();

        const uint32_t base = sb + (kc & 1) * BUFSZ;
        uint32_t ah[2][4], al[2][4], bh[2][4], bl[2][4];
        #pragma unroll
        for (int i = 0; i < 2; i++) {
            ldm_x4(ah[i], base + OA_H + a_off + i * 16 * PITCH);
            ldm_x4(al[i], base + OA_L + a_off + i * 16 * PITCH);
        }
        #pragma unroll
        for (int j = 0; j < 2; j++) {
            ldm_x4(bh[j], base + OW_H + b_off + j * 16 * PITCH);
            ldm_x4(bl[j], base + OW_L + b_off + j * 16 * PITCH);
        }

        #pragma unroll
        for (int i = 0; i < 2; i++)
            #pragma unroll
            for (int j = 0; j < 4; j++) {
                const uint32_t* ph = &bh[j >> 1][2 * (j & 1)];
                const uint32_t* pl = &bl[j >> 1][2 * (j & 1)];
                mma16816(acc[i][j], ah[i], ph);
                mma16816(acc[i][j], ah[i], pl);
                mma16816(acc[i][j], al[i], ph);
            }
        __syncthreads();
    }

    // epilogue: store E = exp(2 * proj)
    #pragma unroll
    for (int i = 0; i < 2; i++) {
        const int r0 = wm * 32 + i * 16 + (lane >> 2);
        #pragma unroll
        for (int j = 0; j < 4; j++) {
            const int c0 = bn * 64 + wn * 32 + j * 8 + (lane & 3) * 2;
            *(float2*)(C + (size_t)r0 * 512 + c0) =
                make_float2(__expf(2.f * acc[i][j][0]), __expf(2.f * acc[i][j][1]));
            *(float2*)(C + (size_t)(r0 + 8) * 512 + c0) =
                make_float2(__expf(2.f * acc[i][j][2]), __expf(2.f * acc[i][j][3]));
        }
    }
}

// ---------------------------------------------------------------------------
// Score -> unnormalized p = exp(e) in g_a + per-quarter partial sums g_psum.
// e[t,s] = -2 * sum_k Va_k / (1 + Ea[t,k]*Eb[s,k])  (+const, cancels in
// softmax; |e| bounded ~36 -> exp safe in fp32, no max pass).
// Grid (TGT/TT, 4 s-quarters, BB) = 1024 blocks. Tile 128 s-rows x 32 k,
// cp.async DOUBLE-buffERED (36KB) + dp 8KB + va 2KB -> ~46KB, 4 blocks/SM.
// Warp w: rows (w&3)*32+lane, t-pair tg = (w>>2)*2; acc[2].
// ---------------------------------------------------------------------------
#define STW (128 * 36)

__global__ void __launch_bounds__(256, 4) score_kernel(
    const float* __restrict__ Va,
    const int* __restrict__ mask)
{
    __shared__ float s_mp[2 * STW];     // 36 KB
    __shared__ float s_dp[TT * 512];    //  8 KB
    __shared__ float s_va[512];         //  2 KB
    __shared__ float s_red[TT * 4];

    const int b    = blockIdx.z;
    const int q4   = blockIdx.y;        // s-quarter 0..3
    const int t0   = blockIdx.x * TT;
    const int tid  = threadIdx.x;
    const int lane = tid & 31;
    const int w    = tid >> 5;
    const int wr4  = w & 3;             // row-group
    const int tg   = (w >> 2) * 2;      // t-pair base

    {
        const float4* dpg = (const float4*)(g_dp + (size_t)(b * TGT + t0) * 512);
        ((float4*)s_dp)[tid]       = dpg[tid];
        ((float4*)s_dp)[tid + 256] = dpg[tid + 256];
        if (tid < 128) ((float4*)s_va)[tid] = ((const float4*)Va)[tid];
    }

    const float* mpg = g_mp + (size_t)(b * SRC + q4 * 128) * 512;

    // loader: 1024 float4 per chunk, 4 per thread
    const int lr[4] = { (tid + 0) >> 3, (tid + 256) >> 3, (tid + 512) >> 3, (tid + 768) >> 3 };
    const int lc4   = (tid & 7) << 2;

    auto issue = [&](int kc, int buf) {
        float* dst = s_mp + buf * STW;
        const float* src = mpg + kc * 32;
        #pragma unroll
        for (int i = 0; i < 4; i++)
            cp_async16(dst + lr[i] * 36 + lc4, src + (size_t)lr[i] * 512 + lc4);
        CP_COMMIT();
    };

    issue(0, 0);

    float acc[2] = {0.f, 0.f};
    const int myrow = wr4 * 32 + lane;

    for (int c = 0; c < 16; c++) {
        if (c < 15) { issue(c + 1, (c + 1) & 1); CP_WAIT1(); }
        else        { CP_WAIT0(); }
        __syncthreads();

        const float* mrow_s = s_mp + (c & 1) * STW + myrow * 36;
        const int kc = c * 32;
        #pragma unroll
        for (int k = 0; k < 32; k += 4) {
            float4 m4 = *(const float4*)(mrow_s + k);           // Eb
            float4 v4 = *(const float4*)(s_va + kc + k);
            #pragma unroll
            for (int tt = 0; tt < 2; tt++) {
                float4 d4 = *(const float4*)(s_dp + (tg + tt) * 512 + kc + k);  // Ea
                float r0v = fast_rcp(fmaf(d4.x, m4.x, 1.f));
                float r1v = fast_rcp(fmaf(d4.y, m4.y, 1.f));
                float r2v = fast_rcp(fmaf(d4.z, m4.z, 1.f));
                float r3v = fast_rcp(fmaf(d4.w, m4.w, 1.f));
                acc[tt] = fmaf(v4.x, r0v, acc[tt]);
                acc[tt] = fmaf(v4.y, r1v, acc[tt]);
                acc[tt] = fmaf(v4.z, r2v, acc[tt]);
                acc[tt] = fmaf(v4.w, r3v, acc[tt]);
            }
        }
        __syncthreads();   // compute done before buffer refilled
    }

    // p = exp(-2*acc), masked to 0
    const int sg = q4 * 128 + myrow;
    const bool mok = (mask[b * SRC + sg] != 0);
    float p[2];
    #pragma unroll
    for (int tt = 0; tt < 2; tt++)
        p[tt] = mok ? __expf(-2.f * acc[tt]) : 0.f;

    // per-t partial sums over this block's 128 s (4 warps share each t)
    #pragma unroll
    for (int tt = 0; tt < 2; tt++) {
        float s = p[tt];
        #pragma unroll
        for (int o = 16; o; o >>= 1) s += __shfl_xor_sync(0xffffffffu, s, o);
        if (lane == 0) s_red[(tg + tt) * 4 + wr4] = s;
    }
    __syncthreads();
    if (tid < TT) {
        const float* r = s_red + tid * 4;
        g_psum[(b * TGT + t0 + tid) * 4 + q4] = r[0] + r[1] + r[2] + r[3];
    }

    #pragma unroll
    for (int tt = 0; tt < 2; tt++)
        g_a[(size_t)(b * TGT + t0 + tg + tt) * SRC + sg] = p[tt];
}

// ---------------------------------------------------------------------------
// Context GEMM + normalization:
// out[b,t,:] = (g_a[b,t,:] @ memory[b]) / sum_q psum[b,t,q]
// ---------------------------------------------------------------------------
__global__ void __launch_bounds__(256) context_kernel(
    const float* __restrict__ memory,
    float* __restrict__ out)
{
    __shared__ float As[64 * 32];
    __shared__ float Bs[32 * 32];

    const int cb  = blockIdx.x;
    const int tb  = blockIdx.y;
    const int b   = blockIdx.z;
    const int tid = threadIdx.x;
    const int col = tid & 31;
    const int tr0 = (tid >> 5) * 8;

    const float* Ab = g_a + (size_t)(b * TGT + tb * 64) * SRC;
    const float* Bb = memory + (size_t)b * SRC * ED + cb * 32;

    const int ar = tid >> 2;
    const int ac = (tid & 3) * 8;
    const int br = tid >> 3;
    const int bc = (tid & 7) * 4;

    float acc[8];
    #pragma unroll
    for (int i = 0; i < 8; i++) acc[i] = 0.f;

    for (int sc = 0; sc < SRC; sc += 32) {
        __syncthreads();
        *(float4*)(As + ar * 32 + ac)     = *(const float4*)(Ab + (size_t)ar * SRC + sc + ac);
        *(float4*)(As + ar * 32 + ac + 4) = *(const float4*)(Ab + (size_t)ar * SRC + sc + ac + 4);
        *(float4*)(Bs + br * 32 + bc)     = *(const float4*)(Bb + (size_t)(sc + br) * ED + bc);
        __syncthreads();

        #pragma unroll
        for (int s = 0; s < 32; s++) {
            float bv = Bs[s * 32 + col];
            #pragma unroll
            for (int i = 0; i < 8; i++)
                acc[i] = fmaf(As[(tr0 + i) * 32 + s], bv, acc[i]);
        }
    }

    #pragma unroll
    for (int i = 0; i < 8; i++) {
        const int t = tb * 64 + tr0 + i;
        const float* ps = g_psum + (b * TGT + t) * 4;
        const float inv = 1.f / (ps[0] + ps[1] + ps[2] + ps[3]);
        out[(size_t)(b * TGT + t) * ED + cb * 32 + col] = acc[i] * inv;
    }
}

// ---------------------------------------------------------------------------
extern "C" void kernel_launch(void* const* d_in, const int* in_sizes, int n_in,
                              void* d_out, int out_size)
{
    const float* memory = (const float*)d_in[0];
    const float* dec    = (const float*)d_in[1];
    const int*   mask   = (const int*)d_in[2];
    const float* Wa     = (const float*)d_in[3];
    const float* Va     = (const float*)d_in[4];
    float*       out    = (float*)d_out;

    (void)in_sizes; (void)n_in; (void)out_size;

    conv_a<<<2560, 256>>>(memory, dec);
    conv_w<<<dim3(16, 16, 2), dim3(32, 8)>>>(Wa);
    gemm_tc<<<dim3(8, 40), 256>>>();
    score_kernel<<<dim3(TGT / TT, 4, BB), 256>>>(Va, mask);
    context_kernel<<<dim3(16, 2, BB), 256>>>(memory, out);
}